// round 13
// baseline (speedup 1.0000x reference)
#include <cuda_runtime.h>
#include <cuda_fp16.h>
#include <cstdint>

// ---------------------------------------------------------------------------
// FixedTopKLoRALinear: out = x@W^T + bias + softtopk(x@A^T)@B^T
// x[8192,4096], A[64,4096], B[4096,64], W[4096,4096], bias[4096]
//
// Two-level INT8 (h + l/128, per-row scales) on mma.sync m16n8k32.s8:
// 3 IMMAs replace 2 HMMAs' worth of work at 2x FLOP/instruction density.
// Main GEMM: 128x128 CTA, 8 warps (2m x 4n), warp 64x32, K-tile=128 s8,
// 2-stage cp.async, ldmatrix.x4 (s8 via b16 byte-pairs), pitch-36 smem.
// LoRA applied as one fp16 k-tile mma in the epilogue (seeded with scaled
// int result), + bias. tcgen05/wgmma unavailable (plain sm_103 target).
// ---------------------------------------------------------------------------

#define D_IN_C   4096
#define D_IN_W   1024          // uint32 words per int8 row (4096 s8)
#define N_FIX    4096
#define R_C      64
#define R_P      32            // fp16 pairs per zs/B row
#define KSEL_C   16
#define TEMP_C   0.1f
#define MAX_M    8192
#define PITCH    36            // uint32 words per smem row (128B data + pad)

// Scratch (allocation-free: device globals)
__device__ uint32_t g_xh8[MAX_M * D_IN_W];
__device__ uint32_t g_xl8[MAX_M * D_IN_W];
__device__ uint32_t g_wh8[N_FIX * D_IN_W];
__device__ uint32_t g_wl8[N_FIX * D_IN_W];
__device__ uint32_t g_ah8[R_C * D_IN_W];
__device__ uint32_t g_al8[R_C * D_IN_W];
__device__ float    g_xs[MAX_M];
__device__ float    g_ws[N_FIX];
__device__ float    g_as[R_C];
__device__ uint32_t g_bh [N_FIX * R_P];     // B as fp16 pairs
__device__ float    g_z  [MAX_M * R_C];
__device__ uint32_t g_zsh[MAX_M * R_P];     // z_sparse as fp16 pairs

// ---------------------------------------------------------------------------
__device__ __forceinline__ uint32_t pack2(float a, float b) {
    __half2 h = __floats2half2_rn(a, b);
    return *(uint32_t*)&h;
}

__device__ __forceinline__ void mma_s8(int32_t* d, const uint32_t* a, const uint32_t* b) {
    asm volatile(
        "mma.sync.aligned.m16n8k32.row.col.s32.s8.s8.s32 "
        "{%0,%1,%2,%3},{%4,%5,%6,%7},{%8,%9},{%0,%1,%2,%3};"
        : "+r"(d[0]), "+r"(d[1]), "+r"(d[2]), "+r"(d[3])
        : "r"(a[0]), "r"(a[1]), "r"(a[2]), "r"(a[3]), "r"(b[0]), "r"(b[1]));
}

__device__ __forceinline__ void mma_f16(float* d, const uint32_t* a, const uint32_t* b) {
    asm volatile(
        "mma.sync.aligned.m16n8k16.row.col.f32.f16.f16.f32 "
        "{%0,%1,%2,%3},{%4,%5,%6,%7},{%8,%9},{%0,%1,%2,%3};"
        : "+f"(d[0]), "+f"(d[1]), "+f"(d[2]), "+f"(d[3])
        : "r"(a[0]), "r"(a[1]), "r"(a[2]), "r"(a[3]), "r"(b[0]), "r"(b[1]));
}

__device__ __forceinline__ void ldmatrix4(uint32_t* r, uint32_t addr) {
    asm volatile("ldmatrix.sync.aligned.m8n8.x4.shared.b16 {%0,%1,%2,%3}, [%4];"
                 : "=r"(r[0]), "=r"(r[1]), "=r"(r[2]), "=r"(r[3]) : "r"(addr));
}

__device__ __forceinline__ void cp_async16(uint32_t* dst_smem, const uint32_t* src_gmem) {
    uint32_t s = (uint32_t)__cvta_generic_to_shared(dst_smem);
    asm volatile("cp.async.cg.shared.global [%0], [%1], 16;\n" :: "r"(s), "l"(src_gmem));
}
#define CPA_COMMIT() asm volatile("cp.async.commit_group;" ::: "memory")
#define CPA_WAIT(n)  asm volatile("cp.async.wait_group %0;" :: "n"(n) : "memory")

// ---------------------------------------------------------------------------
// Two-level int8 quantization: one row (4096 floats) per 128-thread block.
// x = s*(h + l/128), h,l in s8; s = rowmax|x|/127.
// ---------------------------------------------------------------------------
__global__ void quant2_kernel(const float* __restrict__ in,
                              uint32_t* __restrict__ h8,
                              uint32_t* __restrict__ l8,
                              float* __restrict__ scale)
{
    __shared__ float red[4];
    const int row = blockIdx.x;
    const int tid = threadIdx.x;
    const float4* src = (const float4*)(in + (size_t)row * D_IN_C);
    float4 v[8];
    float mx = 0.f;
#pragma unroll
    for (int i = 0; i < 8; i++) {
        v[i] = src[tid + i * 128];
        mx = fmaxf(mx, fmaxf(fmaxf(fabsf(v[i].x), fabsf(v[i].y)),
                             fmaxf(fabsf(v[i].z), fabsf(v[i].w))));
    }
#pragma unroll
    for (int off = 16; off; off >>= 1)
        mx = fmaxf(mx, __shfl_xor_sync(0xffffffffu, mx, off));
    if ((tid & 31) == 0) red[tid >> 5] = mx;
    __syncthreads();
    mx = fmaxf(fmaxf(red[0], red[1]), fmaxf(red[2], red[3]));
    const float s   = (mx > 0.f) ? mx / 127.f : 1.f;
    const float inv = (mx > 0.f) ? 127.f / mx : 0.f;
    if (tid == 0) scale[row] = s;

    uint32_t* hr = h8 + (size_t)row * D_IN_W;
    uint32_t* lr = l8 + (size_t)row * D_IN_W;
#pragma unroll
    for (int i = 0; i < 8; i++) {
        float f[4] = {v[i].x * inv, v[i].y * inv, v[i].z * inv, v[i].w * inv};
        uint32_t hp = 0, lp = 0;
#pragma unroll
        for (int j = 0; j < 4; j++) {
            float fh = rintf(f[j]);
            int hi = (int)fh;
            int lo = (int)rintf((f[j] - fh) * 128.f);
            hp |= ((uint32_t)hi & 0xFFu) << (8 * j);
            lp |= ((uint32_t)lo & 0xFFu) << (8 * j);
        }
        hr[tid + i * 128] = hp;
        lr[tid + i * 128] = lp;
    }
}

// ===========================================================================
// MAIN GEMM (int8 two-level): 128x128 CTA, 256 thr, 8 warps (2m x 4n),
// warp tile 64x32 (MT=4, NT=4). K-tile = 128 s8.
// Smem stage rows: [Ah 0-127 | Al 128-255 | Bh 256-383 | Bl 384-511].
// Epilogue: scale s32 accs -> f32, then one fp16 LoRA k-tile mma, + bias.
// ===========================================================================
#define SROWS_M  512
#define STGW_M   (SROWS_M * PITCH)

__global__ void __launch_bounds__(256, 1)
gemm_main_i8(const float* __restrict__ bias, float* __restrict__ out)
{
    extern __shared__ uint32_t smem[];
    const int tid  = threadIdx.x;
    const int lane = tid & 31;
    const int wid  = tid >> 5;
    const int wm   = wid >> 2;     // 0..1 -> m offset 64
    const int wn   = wid & 3;      // 0..3 -> n offset 32

    const int bm = blockIdx.y * 128;
    const int bn = blockIdx.x * 128;

    const int la_row = (lane & 7) + ((lane >> 3) & 1) * 8;
    const int la_kp  = (lane >> 4) * 4;
    const int lb_row = (lane & 7) + (lane >> 4) * 8;
    const int lb_kp  = ((lane >> 3) & 1) * 4;

    const uint32_t smem_u = (uint32_t)__cvta_generic_to_shared(smem);
    const uint32_t aH = smem_u + 4u * ((uint32_t)(wm * 64 + la_row) * PITCH + la_kp);
    const uint32_t aL = aH + 4u * 128 * PITCH;
    const uint32_t bH = smem_u + 4u * ((uint32_t)(256 + wn * 32 + lb_row) * PITCH + lb_kp);
    const uint32_t bL = bH + 4u * 128 * PITCH;

    int32_t acc1[4][4][4], acc2[4][4][4];
#pragma unroll
    for (int mt = 0; mt < 4; mt++)
#pragma unroll
        for (int nt = 0; nt < 4; nt++)
#pragma unroll
            for (int e = 0; e < 4; e++) { acc1[mt][nt][e] = 0; acc2[mt][nt][e] = 0; }

    auto issue = [&](int kb, int s) {
        uint32_t* sp = smem + s * STGW_M;
#pragma unroll
        for (int i = 0; i < 16; i++) {
            int linear = tid + i * 256;
            int row = linear >> 3;
            int cv  = (linear & 7) << 2;
            int r   = row & 127;
            const uint32_t* src =
                (i < 4)  ? g_xh8 + (size_t)(bm + r) * D_IN_W + kb * 32 + cv :
                (i < 8)  ? g_xl8 + (size_t)(bm + r) * D_IN_W + kb * 32 + cv :
                (i < 12) ? g_wh8 + (size_t)(bn + r) * D_IN_W + kb * 32 + cv :
                           g_wl8 + (size_t)(bn + r) * D_IN_W + kb * 32 + cv;
            cp_async16(&sp[row * PITCH + cv], src);
        }
        CPA_COMMIT();
    };

    issue(0, 0);

    const int KT = D_IN_C / 128;   // 32
    for (int kb = 0; kb < KT; kb++) {
        const int s = kb & 1;
        if (kb + 1 < KT) { issue(kb + 1, s ^ 1); CPA_WAIT(1); }
        else             { CPA_WAIT(0); }
        __syncthreads();

        const uint32_t o = 4u * (uint32_t)(s * STGW_M);
        const uint32_t saH = aH + o, saL = aL + o, sbH = bH + o, sbL = bL + o;

#pragma unroll
        for (int kk = 0; kk < 4; kk++) {
            const uint32_t ko = 4u * (uint32_t)(kk * 8);
            uint32_t ah[4][4], al[4][4], bh[4][2], bl[4][2];
#pragma unroll
            for (int mt = 0; mt < 4; mt++) {
                ldmatrix4(ah[mt], saH + 4u * (uint32_t)(mt * 16 * PITCH) + ko);
                ldmatrix4(al[mt], saL + 4u * (uint32_t)(mt * 16 * PITCH) + ko);
            }
#pragma unroll
            for (int np = 0; np < 2; np++) {
                uint32_t r[4];
                ldmatrix4(r, sbH + 4u * (uint32_t)(np * 16 * PITCH) + ko);
                bh[np * 2 + 0][0] = r[0]; bh[np * 2 + 0][1] = r[1];
                bh[np * 2 + 1][0] = r[2]; bh[np * 2 + 1][1] = r[3];
                ldmatrix4(r, sbL + 4u * (uint32_t)(np * 16 * PITCH) + ko);
                bl[np * 2 + 0][0] = r[0]; bl[np * 2 + 0][1] = r[1];
                bl[np * 2 + 1][0] = r[2]; bl[np * 2 + 1][1] = r[3];
            }
#pragma unroll
            for (int mt = 0; mt < 4; mt++)
#pragma unroll
                for (int nt = 0; nt < 4; nt++) {
                    mma_s8(acc1[mt][nt], ah[mt], bh[nt]);
                    mma_s8(acc2[mt][nt], ah[mt], bl[nt]);
                    mma_s8(acc2[mt][nt], al[mt], bh[nt]);
                }
        }
        __syncthreads();
    }

    // ---- epilogue: scale to f32 ----
    float sxv[4][2], swv[4][2];
#pragma unroll
    for (int mt = 0; mt < 4; mt++) {
        int r0 = bm + wm * 64 + mt * 16 + (lane >> 2);
        sxv[mt][0] = __ldg(&g_xs[r0]);
        sxv[mt][1] = __ldg(&g_xs[r0 + 8]);
    }
#pragma unroll
    for (int nt = 0; nt < 4; nt++) {
        int c0 = bn + wn * 32 + nt * 8 + (lane & 3) * 2;
        swv[nt][0] = __ldg(&g_ws[c0]);
        swv[nt][1] = __ldg(&g_ws[c0 + 1]);
    }
    float accf[4][4][4];
#pragma unroll
    for (int mt = 0; mt < 4; mt++)
#pragma unroll
        for (int nt = 0; nt < 4; nt++)
#pragma unroll
            for (int e = 0; e < 4; e++)
                accf[mt][nt][e] = sxv[mt][e >> 1] * swv[nt][e & 1] *
                    ((float)acc1[mt][nt][e] + (float)acc2[mt][nt][e] * (1.0f / 128.0f));

    // ---- LoRA fp16 k-tile: zs rows 0-127, B-fp16 rows 128-255 in stage 0 ----
    {
        uint32_t* sp = smem;
#pragma unroll
        for (int i = 0; i < 8; i++) {
            int linear = tid + i * 256;
            int row = linear >> 3;
            int cv  = (linear & 7) << 2;
            int r   = row & 127;
            const uint32_t* src = (i < 4)
                ? g_zsh + (size_t)(bm + r) * R_P + cv
                : g_bh  + (size_t)(bn + r) * R_P + cv;
            cp_async16(&sp[row * PITCH + cv], src);
        }
        CPA_COMMIT(); CPA_WAIT(0);
        __syncthreads();
    }
    {
        const uint32_t eA = smem_u + 4u * ((uint32_t)(wm * 64 + la_row) * PITCH + la_kp);
        const uint32_t eB = smem_u + 4u * ((uint32_t)(128 + wn * 32 + lb_row) * PITCH + lb_kp);
#pragma unroll
        for (int kk = 0; kk < 4; kk++) {
            const uint32_t ko = 4u * (uint32_t)(kk * 8);
            uint32_t af[4][4], bf[4][2];
#pragma unroll
            for (int mt = 0; mt < 4; mt++)
                ldmatrix4(af[mt], eA + 4u * (uint32_t)(mt * 16 * PITCH) + ko);
#pragma unroll
            for (int np = 0; np < 2; np++) {
                uint32_t r[4];
                ldmatrix4(r, eB + 4u * (uint32_t)(np * 16 * PITCH) + ko);
                bf[np * 2 + 0][0] = r[0]; bf[np * 2 + 0][1] = r[1];
                bf[np * 2 + 1][0] = r[2]; bf[np * 2 + 1][1] = r[3];
            }
#pragma unroll
            for (int mt = 0; mt < 4; mt++)
#pragma unroll
                for (int nt = 0; nt < 4; nt++)
                    mma_f16(accf[mt][nt], af[mt], bf[nt]);
        }
    }

    // ---- bias + store ----
#pragma unroll
    for (int mt = 0; mt < 4; mt++) {
#pragma unroll
        for (int nt = 0; nt < 4; nt++) {
            int r0 = bm + wm * 64 + mt * 16 + (lane >> 2);
            int c0 = bn + wn * 32 + nt * 8 + (lane & 3) * 2;
            float b0 = __ldg(&bias[c0]), b1 = __ldg(&bias[c0 + 1]);
            float2 v0 = make_float2(accf[mt][nt][0] + b0, accf[mt][nt][1] + b1);
            float2 v1 = make_float2(accf[mt][nt][2] + b0, accf[mt][nt][3] + b1);
            *(float2*)&out[(size_t)r0 * N_FIX + c0]       = v0;
            *(float2*)&out[(size_t)(r0 + 8) * N_FIX + c0] = v1;
        }
    }
}

// ===========================================================================
// Z-GEMM (int8 two-level): z = x @ A^T, 64x64 CTA, 128 thr, 4 warps (2x2),
// warp tile 32x32 (MT=2, NT=4). Smem rows: [Ah 0-63|Al 64-127|Bh 128-191|Bl 192-255].
// ===========================================================================
#define SROWS_Z  256
#define STGW_Z   (SROWS_Z * PITCH)

__global__ void __launch_bounds__(128)
gemm_z_i8()
{
    extern __shared__ uint32_t smem[];
    const int tid  = threadIdx.x;
    const int lane = tid & 31;
    const int wid  = tid >> 5;
    const int wm   = wid >> 1;
    const int wn   = wid & 1;
    const int bm   = blockIdx.x * 64;

    const int la_row = (lane & 7) + ((lane >> 3) & 1) * 8;
    const int la_kp  = (lane >> 4) * 4;
    const int lb_row = (lane & 7) + (lane >> 4) * 8;
    const int lb_kp  = ((lane >> 3) & 1) * 4;

    const uint32_t smem_u = (uint32_t)__cvta_generic_to_shared(smem);
    const uint32_t aH = smem_u + 4u * ((uint32_t)(wm * 32 + la_row) * PITCH + la_kp);
    const uint32_t aL = aH + 4u * 64 * PITCH;
    const uint32_t bH = smem_u + 4u * ((uint32_t)(128 + wn * 32 + lb_row) * PITCH + lb_kp);
    const uint32_t bL = bH + 4u * 64 * PITCH;

    int32_t acc1[2][4][4], acc2[2][4][4];
#pragma unroll
    for (int mt = 0; mt < 2; mt++)
#pragma unroll
        for (int nt = 0; nt < 4; nt++)
#pragma unroll
            for (int e = 0; e < 4; e++) { acc1[mt][nt][e] = 0; acc2[mt][nt][e] = 0; }

    auto issue = [&](int kb, int s) {
        uint32_t* sp = smem + s * STGW_Z;
#pragma unroll
        for (int i = 0; i < 16; i++) {
            int linear = tid + i * 128;
            int row = linear >> 3;
            int cv  = (linear & 7) << 2;
            int r   = row & 63;
            const uint32_t* src =
                (i < 4)  ? g_xh8 + (size_t)(bm + r) * D_IN_W + kb * 32 + cv :
                (i < 8)  ? g_xl8 + (size_t)(bm + r) * D_IN_W + kb * 32 + cv :
                (i < 12) ? g_ah8 + (size_t)r * D_IN_W + kb * 32 + cv :
                           g_al8 + (size_t)r * D_IN_W + kb * 32 + cv;
            cp_async16(&sp[row * PITCH + cv], src);
        }
        CPA_COMMIT();
    };

    issue(0, 0);

    const int KT = D_IN_C / 128;
    for (int kb = 0; kb < KT; kb++) {
        const int s = kb & 1;
        if (kb + 1 < KT) { issue(kb + 1, s ^ 1); CPA_WAIT(1); }
        else             { CPA_WAIT(0); }
        __syncthreads();

        const uint32_t o = 4u * (uint32_t)(s * STGW_Z);
        const uint32_t saH = aH + o, saL = aL + o, sbH = bH + o, sbL = bL + o;

#pragma unroll
        for (int kk = 0; kk < 4; kk++) {
            const uint32_t ko = 4u * (uint32_t)(kk * 8);
            uint32_t ah[2][4], al[2][4], bh[4][2], bl[4][2];
#pragma unroll
            for (int mt = 0; mt < 2; mt++) {
                ldmatrix4(ah[mt], saH + 4u * (uint32_t)(mt * 16 * PITCH) + ko);
                ldmatrix4(al[mt], saL + 4u * (uint32_t)(mt * 16 * PITCH) + ko);
            }
#pragma unroll
            for (int np = 0; np < 2; np++) {
                uint32_t r[4];
                ldmatrix4(r, sbH + 4u * (uint32_t)(np * 16 * PITCH) + ko);
                bh[np * 2 + 0][0] = r[0]; bh[np * 2 + 0][1] = r[1];
                bh[np * 2 + 1][0] = r[2]; bh[np * 2 + 1][1] = r[3];
                ldmatrix4(r, sbL + 4u * (uint32_t)(np * 16 * PITCH) + ko);
                bl[np * 2 + 0][0] = r[0]; bl[np * 2 + 0][1] = r[1];
                bl[np * 2 + 1][0] = r[2]; bl[np * 2 + 1][1] = r[3];
            }
#pragma unroll
            for (int mt = 0; mt < 2; mt++)
#pragma unroll
                for (int nt = 0; nt < 4; nt++) {
                    mma_s8(acc1[mt][nt], ah[mt], bh[nt]);
                    mma_s8(acc2[mt][nt], ah[mt], bl[nt]);
                    mma_s8(acc2[mt][nt], al[mt], bh[nt]);
                }
        }
        __syncthreads();
    }

#pragma unroll
    for (int mt = 0; mt < 2; mt++) {
#pragma unroll
        for (int nt = 0; nt < 4; nt++) {
            int r0 = bm + wm * 32 + mt * 16 + (lane >> 2);
            int c0 = wn * 32 + nt * 8 + (lane & 3) * 2;
            float sa0 = __ldg(&g_as[c0]), sa1 = __ldg(&g_as[c0 + 1]);
            float sx0 = __ldg(&g_xs[r0]), sx1 = __ldg(&g_xs[r0 + 8]);
            float2 v0, v1;
            v0.x = sx0 * sa0 * ((float)acc1[mt][nt][0] + (float)acc2[mt][nt][0] * (1.0f/128.0f));
            v0.y = sx0 * sa1 * ((float)acc1[mt][nt][1] + (float)acc2[mt][nt][1] * (1.0f/128.0f));
            v1.x = sx1 * sa0 * ((float)acc1[mt][nt][2] + (float)acc2[mt][nt][2] * (1.0f/128.0f));
            v1.y = sx1 * sa1 * ((float)acc1[mt][nt][3] + (float)acc2[mt][nt][3] * (1.0f/128.0f));
            *(float2*)&g_z[(size_t)r0 * R_C + c0]       = v0;
            *(float2*)&g_z[(size_t)(r0 + 8) * R_C + c0] = v1;
        }
    }
}

// ---------------------------------------------------------------------------
__global__ void cvt_f16_kernel(const float4* __restrict__ in,
                               uint2* __restrict__ out, int n4)
{
    int i = blockIdx.x * blockDim.x + threadIdx.x;
    const int stride = gridDim.x * blockDim.x;
    for (; i < n4; i += stride) {
        float4 v = in[i];
        uint2 o;
        o.x = pack2(v.x, v.y);
        o.y = pack2(v.z, v.w);
        out[i] = o;
    }
}

// ---------------------------------------------------------------------------
// Soft top-k: one warp per row of 64 z values; exact 16th-largest |z|.
// ---------------------------------------------------------------------------
__global__ void topk_mask_kernel(int M)
{
    const int row  = blockIdx.x * 8 + (threadIdx.x >> 5);
    const int lane = threadIdx.x & 31;
    if (row >= M) return;

    float z0 = g_z[row * R_C + lane];
    float z1 = g_z[row * R_C + lane + 32];
    float v0 = fabsf(z0), v1 = fabsf(z1);
    bool a0 = true, a1 = true;
    float thr = 0.0f;

#pragma unroll 1
    for (int it = 0; it < KSEL_C; it++) {
        float m = fmaxf(a0 ? v0 : -1.0f, a1 ? v1 : -1.0f);
#pragma unroll
        for (int off = 16; off; off >>= 1)
            m = fmaxf(m, __shfl_xor_sync(0xffffffffu, m, off));
        thr = m;
        unsigned b = __ballot_sync(0xffffffffu, a0 && v0 == m);
        if (b) {
            if (lane == (__ffs(b) - 1)) a0 = false;
        } else {
            unsigned b2 = __ballot_sync(0xffffffffu, a1 && v1 == m);
            if (lane == (__ffs(b2) - 1)) a1 = false;
        }
    }

    const float inv_t = 1.0f / TEMP_C;
    float m0 = 1.0f / (1.0f + expf(-(v0 - thr) * inv_t));
    float m1 = 1.0f / (1.0f + expf(-(v1 - thr) * inv_t));
    __half* zsh = (__half*)g_zsh;
    zsh[row * R_C + lane]      = __float2half_rn(z0 * m0);
    zsh[row * R_C + lane + 32] = __float2half_rn(z1 * m1);
}

// ---------------------------------------------------------------------------
extern "C" void kernel_launch(void* const* d_in, const int* in_sizes, int n_in,
                              void* d_out, int out_size)
{
    const float* x    = (const float*)d_in[0];
    const float* Amat = (const float*)d_in[1];
    const float* Bmat = (const float*)d_in[2];
    const float* Wmat = (const float*)d_in[3];
    const float* bias = (const float*)d_in[4];
    float* out = (float*)d_out;

    const int M = in_sizes[0] / D_IN_C;          // 8192
    const int N = in_sizes[4];                   // 4096

    uint32_t *xh8, *xl8, *wh8, *wl8, *ah8, *al8, *bh;
    float *xs, *ws, *as_;
    cudaGetSymbolAddress((void**)&xh8, g_xh8);
    cudaGetSymbolAddress((void**)&xl8, g_xl8);
    cudaGetSymbolAddress((void**)&wh8, g_wh8);
    cudaGetSymbolAddress((void**)&wl8, g_wl8);
    cudaGetSymbolAddress((void**)&ah8, g_ah8);
    cudaGetSymbolAddress((void**)&al8, g_al8);
    cudaGetSymbolAddress((void**)&bh,  g_bh);
    cudaGetSymbolAddress((void**)&xs,  g_xs);
    cudaGetSymbolAddress((void**)&ws,  g_ws);
    cudaGetSymbolAddress((void**)&as_, g_as);

    // 0) two-level int8 quantization + B fp16 cvt
    quant2_kernel<<<M, 128>>>(x,    xh8, xl8, xs);
    quant2_kernel<<<N, 128>>>(Wmat, wh8, wl8, ws);
    quant2_kernel<<<R_C, 128>>>(Amat, ah8, al8, as_);
    cvt_f16_kernel<<<256, 256>>>((const float4*)Bmat, (uint2*)bh, N * R_C / 4);

    constexpr int SMEM_MAIN = 2 * STGW_M * 4;   // 147456 B
    constexpr int SMEM_Z    = 2 * STGW_Z * 4;   // 73728 B
    cudaFuncSetAttribute(gemm_main_i8,
                         cudaFuncAttributeMaxDynamicSharedMemorySize, SMEM_MAIN);
    cudaFuncSetAttribute(gemm_z_i8,
                         cudaFuncAttributeMaxDynamicSharedMemorySize, SMEM_Z);

    // 1) z = x @ A^T
    gemm_z_i8<<<M / 64, 128, SMEM_Z>>>();

    // 2) soft top-k -> zs fp16
    topk_mask_kernel<<<M / 8, 256>>>(M);

    // 3) out = x @ W^T + bias + zs @ B^T (LoRA in epilogue)
    {
        dim3 grid(N / 128, M / 128);
        gemm_main_i8<<<grid, 256, SMEM_MAIN>>>(bias, out);
    }
}

// round 14
// speedup vs baseline: 6.9318x; 6.9318x over previous
#include <cuda_runtime.h>
#include <cuda_fp16.h>
#include <cstdint>

// ---------------------------------------------------------------------------
// FixedTopKLoRALinear: out = x@W^T + bias + softtopk(x@A^T)@B^T
// x[8192,4096], A[64,4096], B[4096,64], W[4096,4096], bias[4096]
//
// fp16 m16n8k16 mma.sync, fp32 accum (proven: legacy HMMA pipe is
// instruction-rate-pinned; int8/fp8/tcgen05 alternatives all ruled out).
// 3 launches: (1) cvt W/A/B -> fp16; (2) fused z-kernel: x fp32->fp16 cvt
// + z = x@A^T + soft-topk -> zs fp16; (3) main GEMM with LoRA as one extra
// K-tile + bias (R11 893.9us structure).
// ---------------------------------------------------------------------------

#define D_IN_C   4096
#define D_IN_P   2048          // fp16 pairs per x/W/A row
#define N_FIX    4096
#define R_C      64
#define R_P      32            // fp16 pairs per zs/B row
#define KSEL_C   16
#define TEMP_C   0.1f
#define MAX_M    8192
#define PITCH    36            // uint32 words per smem row

// Scratch (allocation-free: device globals)
__device__ uint32_t g_xh [MAX_M * D_IN_P];
__device__ uint32_t g_wh [N_FIX * D_IN_P];
__device__ uint32_t g_ah [R_C   * D_IN_P];
__device__ uint32_t g_bh [N_FIX * R_P];
__device__ uint32_t g_zsh[MAX_M * R_P];

// ---------------------------------------------------------------------------
__device__ __forceinline__ uint32_t pack2(float a, float b) {
    __half2 h = __floats2half2_rn(a, b);
    return *(uint32_t*)&h;
}

__device__ __forceinline__ void mma_f16(float* d, const uint32_t* a, const uint32_t* b) {
    asm volatile(
        "mma.sync.aligned.m16n8k16.row.col.f32.f16.f16.f32 "
        "{%0,%1,%2,%3},{%4,%5,%6,%7},{%8,%9},{%0,%1,%2,%3};"
        : "+f"(d[0]), "+f"(d[1]), "+f"(d[2]), "+f"(d[3])
        : "r"(a[0]), "r"(a[1]), "r"(a[2]), "r"(a[3]), "r"(b[0]), "r"(b[1]));
}

__device__ __forceinline__ void cp_async16(uint32_t* dst_smem, const uint32_t* src_gmem) {
    uint32_t s = (uint32_t)__cvta_generic_to_shared(dst_smem);
    asm volatile("cp.async.cg.shared.global [%0], [%1], 16;\n" :: "r"(s), "l"(src_gmem));
}
#define CPA_COMMIT() asm volatile("cp.async.commit_group;" ::: "memory")
#define CPA_WAIT(n)  asm volatile("cp.async.wait_group %0;" :: "n"(n) : "memory")

// ===========================================================================
// Kernel 1: convert W, A, B (fp32 -> fp16 pairs) in one launch.
// ===========================================================================
__global__ void cvt_wab_kernel(const float4* __restrict__ W,
                               const float4* __restrict__ A,
                               const float4* __restrict__ B)
{
    const int nW = N_FIX * D_IN_C / 4;     // 4194304
    const int nA = R_C * D_IN_C / 4;       // 65536
    const int nB = N_FIX * R_C / 4;        // 65536
    const int total = nW + nA + nB;
    int i = blockIdx.x * blockDim.x + threadIdx.x;
    const int stride = gridDim.x * blockDim.x;
    for (; i < total; i += stride) {
        const float4* src; uint2* dst; int j;
        if (i < nW)           { src = W; dst = (uint2*)g_wh; j = i; }
        else if (i < nW + nA) { src = A; dst = (uint2*)g_ah; j = i - nW; }
        else                  { src = B; dst = (uint2*)g_bh; j = i - nW - nA; }
        float4 v = src[j];
        uint2 o;
        o.x = pack2(v.x, v.y);
        o.y = pack2(v.z, v.w);
        dst[j] = o;
    }
}

// ===========================================================================
// Kernel 2: fused z pipeline. 64-row blocks, 128 threads, 4 warps (2m x 2n),
// warp tile 32x32 (MT=2, NT=4). Per K-tile (64 floats):
//   LDG x fp32 (prefetched) -> cvt -> STS (own MMA) + STG xh (for main GEMM)
//   cp.async A-matrix fp16 tile.
// Epilogue: z -> smem, exact 16th-largest |z| soft mask, zs fp16 out.
// ===========================================================================
__global__ void __launch_bounds__(128)
z_fused_kernel(const float4* __restrict__ x)
{
    extern __shared__ uint32_t smem[];
    uint32_t* As = smem;                  // [2][64][PITCH]
    uint32_t* Bs = smem + 2 * 64 * PITCH; // [2][64][PITCH]
    float*    zbuf = (float*)smem;        // [64][65], aliased after MMAs

    const int tid  = threadIdx.x;
    const int lane = tid & 31;
    const int wid  = tid >> 5;
    const int wm   = wid >> 1;
    const int wn   = wid & 1;
    const int bm   = blockIdx.x * 64;

    const int col4 = tid & 15;        // f4 column within k-tile
    const int row0 = tid >> 4;        // base row (thread handles rows rowo+8i)

    float acc[2][4][4];
#pragma unroll
    for (int mt = 0; mt < 2; mt++)
#pragma unroll
        for (int nt = 0; nt < 4; nt++)
#pragma unroll
            for (int e = 0; e < 4; e++) acc[mt][nt][e] = 0.0f;

    auto ldg_x = [&](int kb, float4* r) {
#pragma unroll
        for (int i = 0; i < 8; i++)
            r[i] = x[(size_t)(bm + row0 + i * 8) * 1024 + kb * 16 + col4];
    };
    auto cpa_b = [&](int kb, int s) {
        uint32_t* bs = Bs + s * 64 * PITCH;
#pragma unroll
        for (int i = 0; i < 4; i++) {
            int linear = tid + i * 128;
            int row = linear >> 3;
            int cv  = (linear & 7) << 2;
            cp_async16(&bs[row * PITCH + cv],
                       g_ah + (size_t)row * D_IN_P + kb * 32 + cv);
        }
        CPA_COMMIT();
    };
    auto sts_stg = [&](int kb, int s, const float4* r) {
        uint32_t* as = As + s * 64 * PITCH;
        uint2* xo = (uint2*)g_xh;
#pragma unroll
        for (int i = 0; i < 8; i++) {
            uint2 v;
            v.x = pack2(r[i].x, r[i].y);
            v.y = pack2(r[i].z, r[i].w);
            int row = row0 + i * 8;
            *(uint2*)&as[row * PITCH + col4 * 2] = v;
            xo[(size_t)(bm + row) * 1024 + kb * 16 + col4] = v;
        }
    };
    auto mma_tile = [&](int s) {
        const uint32_t* as = As + s * 64 * PITCH + (wm * 32) * PITCH;
        const uint32_t* bs = Bs + s * 64 * PITCH + (wn * 32) * PITCH;
#pragma unroll
        for (int kk = 0; kk < 4; kk++) {
            uint32_t afrag[2][4];
#pragma unroll
            for (int mt = 0; mt < 2; mt++) {
                int r = mt * 16 + (lane >> 2);
                int c = kk * 8 + (lane & 3);
                afrag[mt][0] = as[r * PITCH + c];
                afrag[mt][1] = as[(r + 8) * PITCH + c];
                afrag[mt][2] = as[r * PITCH + c + 4];
                afrag[mt][3] = as[(r + 8) * PITCH + c + 4];
            }
            uint32_t bfrag[4][2];
#pragma unroll
            for (int nt = 0; nt < 4; nt++) {
                int n = nt * 8 + (lane >> 2);
                int c = kk * 8 + (lane & 3);
                bfrag[nt][0] = bs[n * PITCH + c];
                bfrag[nt][1] = bs[n * PITCH + c + 4];
            }
#pragma unroll
            for (int mt = 0; mt < 2; mt++)
#pragma unroll
                for (int nt = 0; nt < 4; nt++)
                    mma_f16(acc[mt][nt], afrag[mt], bfrag[nt]);
        }
    };

    const int KT = D_IN_C / 64;   // 64 (even)
    float4 rA[8], rB[8];
    ldg_x(0, rA);
    cpa_b(0, 0);

    for (int kb2 = 0; kb2 < KT; kb2 += 2) {
        // even tile -> stage 0
        if (kb2 + 1 < KT) { ldg_x(kb2 + 1, rB); cpa_b(kb2 + 1, 1); }
        sts_stg(kb2, 0, rA);
        if (kb2 + 1 < KT) { CPA_WAIT(1); } else { CPA_WAIT(0); }
        __syncthreads();
        mma_tile(0);
        __syncthreads();
        // odd tile -> stage 1
        if (kb2 + 1 < KT) {
            if (kb2 + 2 < KT) { ldg_x(kb2 + 2, rA); cpa_b(kb2 + 2, 0); }
            sts_stg(kb2 + 1, 1, rB);
            if (kb2 + 2 < KT) { CPA_WAIT(1); } else { CPA_WAIT(0); }
            __syncthreads();
            mma_tile(1);
            __syncthreads();
        }
    }

    // ---- z -> smem (pitch 65 floats) ----
#pragma unroll
    for (int mt = 0; mt < 2; mt++)
#pragma unroll
        for (int nt = 0; nt < 4; nt++) {
            int r0 = wm * 32 + mt * 16 + (lane >> 2);
            int c0 = wn * 32 + nt * 8 + (lane & 3) * 2;
            zbuf[r0 * 65 + c0]           = acc[mt][nt][0];
            zbuf[r0 * 65 + c0 + 1]       = acc[mt][nt][1];
            zbuf[(r0 + 8) * 65 + c0]     = acc[mt][nt][2];
            zbuf[(r0 + 8) * 65 + c0 + 1] = acc[mt][nt][3];
        }
    __syncthreads();

    // ---- soft top-k per row; warp w handles rows w*16 .. w*16+15 ----
    const float inv_t = 1.0f / TEMP_C;
    for (int rr = 0; rr < 16; rr++) {
        const int row = wid * 16 + rr;
        float z0 = zbuf[row * 65 + lane];
        float z1 = zbuf[row * 65 + lane + 32];
        float v0 = fabsf(z0), v1 = fabsf(z1);
        bool a0 = true, a1 = true;
        float thr = 0.0f;
#pragma unroll 1
        for (int it = 0; it < KSEL_C; it++) {
            float m = fmaxf(a0 ? v0 : -1.0f, a1 ? v1 : -1.0f);
#pragma unroll
            for (int off = 16; off; off >>= 1)
                m = fmaxf(m, __shfl_xor_sync(0xffffffffu, m, off));
            thr = m;
            unsigned b = __ballot_sync(0xffffffffu, a0 && v0 == m);
            if (b) {
                if (lane == (__ffs(b) - 1)) a0 = false;
            } else {
                unsigned b2 = __ballot_sync(0xffffffffu, a1 && v1 == m);
                if (lane == (__ffs(b2) - 1)) a1 = false;
            }
        }
        float zs0 = z0 * (1.0f / (1.0f + expf(-(v0 - thr) * inv_t)));
        float zs1 = z1 * (1.0f / (1.0f + expf(-(v1 - thr) * inv_t)));
        zbuf[row * 65 + lane]      = zs0;
        zbuf[row * 65 + lane + 32] = zs1;
        __syncwarp();
        // pack pairs: lane p -> cols (2p, 2p+1)
        g_zsh[(size_t)(bm + row) * R_P + lane] =
            pack2(zbuf[row * 65 + 2 * lane], zbuf[row * 65 + 2 * lane + 1]);
        __syncwarp();
    }
}

// ===========================================================================
// Kernel 3: MAIN GEMM (R11 893.9us structure, verbatim).
// 128x128 CTA, 128 threads, 4 warps (2m x 2n), warp tile 64x64.
// K: 64 main tiles + 1 LoRA tile (zs @ B^T). 2-stage cp.async, pitch-36.
// ===========================================================================
__global__ void __launch_bounds__(128)
gemm_main(const float* __restrict__ bias, float* __restrict__ out)
{
    constexpr int BM = 128, BN = 128, MT = 4, NT = 8;
    extern __shared__ uint32_t smem[];
    uint32_t* As = smem;                    // [2][BM][PITCH]
    uint32_t* Bs = smem + 2 * BM * PITCH;   // [2][BN][PITCH]

    const int tid  = threadIdx.x;
    const int lane = tid & 31;
    const int wid  = tid >> 5;
    const int wm   = wid >> 1;
    const int wn   = wid & 1;

    const int bm = blockIdx.y * BM;
    const int bn = blockIdx.x * BN;

    float acc[MT][NT][4];
#pragma unroll
    for (int mt = 0; mt < MT; mt++)
#pragma unroll
        for (int nt = 0; nt < NT; nt++)
#pragma unroll
            for (int i = 0; i < 4; i++) acc[mt][nt][i] = 0.0f;

    const int KT_main = D_IN_C / 64;        // 64
    const int KT = KT_main + 1;             // + LoRA tile

    auto issue_copy = [&](int kb, int stage) {
        uint32_t* as = As + stage * BM * PITCH;
        uint32_t* bs = Bs + stage * BN * PITCH;
        const bool main_k = (kb < KT_main);
#pragma unroll
        for (int i = 0; i < BM / 16; i++) {
            int linear = tid + i * 128;
            int row = linear >> 3;
            int cv  = (linear & 7) << 2;
            const uint32_t* src = main_k
                ? g_xh  + (size_t)(bm + row) * D_IN_P + (size_t)kb * 32 + cv
                : g_zsh + (size_t)(bm + row) * R_P + cv;
            cp_async16(&as[row * PITCH + cv], src);
        }
#pragma unroll
        for (int i = 0; i < BN / 16; i++) {
            int linear = tid + i * 128;
            int row = linear >> 3;
            int cv  = (linear & 7) << 2;
            const uint32_t* src = main_k
                ? g_wh + (size_t)(bn + row) * D_IN_P + (size_t)kb * 32 + cv
                : g_bh + (size_t)(bn + row) * R_P + cv;
            cp_async16(&bs[row * PITCH + cv], src);
        }
        CPA_COMMIT();
    };

    issue_copy(0, 0);

    for (int kb = 0; kb < KT; kb++) {
        const int stage = kb & 1;
        if (kb + 1 < KT) {
            issue_copy(kb + 1, (kb + 1) & 1);
            CPA_WAIT(1);
        } else {
            CPA_WAIT(0);
        }
        __syncthreads();

        const uint32_t* as = As + stage * BM * PITCH + (wm * 64) * PITCH;
        const uint32_t* bs = Bs + stage * BN * PITCH + (wn * 64) * PITCH;

#pragma unroll
        for (int kk = 0; kk < 4; kk++) {
            uint32_t afrag[MT][4];
#pragma unroll
            for (int mt = 0; mt < MT; mt++) {
                int r = mt * 16 + (lane >> 2);
                int c = kk * 8 + (lane & 3);
                afrag[mt][0] = as[r * PITCH + c];
                afrag[mt][1] = as[(r + 8) * PITCH + c];
                afrag[mt][2] = as[r * PITCH + c + 4];
                afrag[mt][3] = as[(r + 8) * PITCH + c + 4];
            }
            uint32_t bfrag[NT][2];
#pragma unroll
            for (int nt = 0; nt < NT; nt++) {
                int n = nt * 8 + (lane >> 2);
                int c = kk * 8 + (lane & 3);
                bfrag[nt][0] = bs[n * PITCH + c];
                bfrag[nt][1] = bs[n * PITCH + c + 4];
            }
#pragma unroll
            for (int mt = 0; mt < MT; mt++)
#pragma unroll
                for (int nt = 0; nt < NT; nt++)
                    mma_f16(acc[mt][nt], afrag[mt], bfrag[nt]);
        }
        __syncthreads();
    }

    // Epilogue: + bias, fp32 store
#pragma unroll
    for (int mt = 0; mt < MT; mt++) {
#pragma unroll
        for (int nt = 0; nt < NT; nt++) {
            int r0 = bm + wm * 64 + mt * 16 + (lane >> 2);
            int c0 = bn + wn * 64 + nt * 8 + (lane & 3) * 2;
            float b0 = __ldg(&bias[c0]), b1 = __ldg(&bias[c0 + 1]);
            float2 v0 = make_float2(acc[mt][nt][0] + b0, acc[mt][nt][1] + b1);
            float2 v1 = make_float2(acc[mt][nt][2] + b0, acc[mt][nt][3] + b1);
            *(float2*)&out[(size_t)r0 * N_FIX + c0]       = v0;
            *(float2*)&out[(size_t)(r0 + 8) * N_FIX + c0] = v1;
        }
    }
}

// ---------------------------------------------------------------------------
extern "C" void kernel_launch(void* const* d_in, const int* in_sizes, int n_in,
                              void* d_out, int out_size)
{
    const float* x    = (const float*)d_in[0];
    const float* Amat = (const float*)d_in[1];
    const float* Bmat = (const float*)d_in[2];
    const float* Wmat = (const float*)d_in[3];
    const float* bias = (const float*)d_in[4];
    float* out = (float*)d_out;

    const int M = in_sizes[0] / D_IN_C;          // 8192
    const int N = in_sizes[4];                   // 4096

    constexpr int SMEM_MAIN = 2 * (128 + 128) * PITCH * 4;  // 73728 B
    constexpr int SMEM_Z    = 2 * (64 + 64) * PITCH * 4;    // 36864 B
    cudaFuncSetAttribute(gemm_main,
                         cudaFuncAttributeMaxDynamicSharedMemorySize, SMEM_MAIN);
    cudaFuncSetAttribute(z_fused_kernel,
                         cudaFuncAttributeMaxDynamicSharedMemorySize, SMEM_Z);

    // 1) W/A/B -> fp16
    cvt_wab_kernel<<<1024, 256>>>((const float4*)Wmat, (const float4*)Amat,
                                  (const float4*)Bmat);

    // 2) x -> fp16 (side output) + z = x@A^T + soft-topk -> zs fp16
    z_fused_kernel<<<M / 64, 128, SMEM_Z>>>((const float4*)x);

    // 3) out = x@W^T + bias + zs@B^T (LoRA = extra K-tile)
    {
        dim3 grid(N / 128, M / 128);
        gemm_main<<<grid, 128, SMEM_MAIN>>>(bias, out);
    }
}

// round 15
// speedup vs baseline: 7.0550x; 1.0178x over previous
#include <cuda_runtime.h>
#include <cuda_fp16.h>
#include <cstdint>

// ---------------------------------------------------------------------------
// FixedTopKLoRALinear: out = x@W^T + bias + softtopk(x@A^T)@B^T
// x[8192,4096], A[64,4096], B[4096,64], W[4096,4096], bias[4096]
//
// fp16 m16n8k16 mma.sync, fp32 accum. Main GEMM is smem-crossbar-bound
// (validated model: 96KB smem traffic per CTA-ktile = 750cyc > 397cyc tensor
// need); it is kept byte-identical to the R14 record (857.8us).
// This round: preprocessing overlap. Launches:
//   (1) cvt A -> fp16 (tiny, ~2us)
//   (2) merged kernel: 128 z-role CTAs (x cvt + z=x@A^T + soft-topk) in
//       parallel with 168 cvt-role CTAs (W/B -> fp16)
//   (3) main GEMM (LoRA fused as one extra K-tile + bias)
// ---------------------------------------------------------------------------

#define D_IN_C   4096
#define D_IN_P   2048          // fp16 pairs per x/W/A row
#define N_FIX    4096
#define R_C      64
#define R_P      32            // fp16 pairs per zs/B row
#define KSEL_C   16
#define TEMP_C   0.1f
#define MAX_M    8192
#define PITCH    36            // uint32 words per smem row

#define Z_BLOCKS   (MAX_M / 64)    // 128
#define CVT_BLOCKS 168

// Scratch (allocation-free: device globals)
__device__ uint32_t g_xh [MAX_M * D_IN_P];
__device__ uint32_t g_wh [N_FIX * D_IN_P];
__device__ uint32_t g_ah [R_C   * D_IN_P];
__device__ uint32_t g_bh [N_FIX * R_P];
__device__ uint32_t g_zsh[MAX_M * R_P];

// ---------------------------------------------------------------------------
__device__ __forceinline__ uint32_t pack2(float a, float b) {
    __half2 h = __floats2half2_rn(a, b);
    return *(uint32_t*)&h;
}

__device__ __forceinline__ void mma_f16(float* d, const uint32_t* a, const uint32_t* b) {
    asm volatile(
        "mma.sync.aligned.m16n8k16.row.col.f32.f16.f16.f32 "
        "{%0,%1,%2,%3},{%4,%5,%6,%7},{%8,%9},{%0,%1,%2,%3};"
        : "+f"(d[0]), "+f"(d[1]), "+f"(d[2]), "+f"(d[3])
        : "r"(a[0]), "r"(a[1]), "r"(a[2]), "r"(a[3]), "r"(b[0]), "r"(b[1]));
}

__device__ __forceinline__ void cp_async16(uint32_t* dst_smem, const uint32_t* src_gmem) {
    uint32_t s = (uint32_t)__cvta_generic_to_shared(dst_smem);
    asm volatile("cp.async.cg.shared.global [%0], [%1], 16;\n" :: "r"(s), "l"(src_gmem));
}
#define CPA_COMMIT() asm volatile("cp.async.commit_group;" ::: "memory")
#define CPA_WAIT(n)  asm volatile("cp.async.wait_group %0;" :: "n"(n) : "memory")

// ===========================================================================
// Kernel 1: convert A (fp32 -> fp16 pairs). 64x4096 = tiny.
// ===========================================================================
__global__ void cvt_a_kernel(const float4* __restrict__ A)
{
    const int n4 = R_C * D_IN_C / 4;   // 65536
    int i = blockIdx.x * blockDim.x + threadIdx.x;
    const int stride = gridDim.x * blockDim.x;
    uint2* dst = (uint2*)g_ah;
    for (; i < n4; i += stride) {
        float4 v = A[i];
        uint2 o;
        o.x = pack2(v.x, v.y);
        o.y = pack2(v.z, v.w);
        dst[i] = o;
    }
}

// ===========================================================================
// Kernel 2 (merged): blockIdx < Z_BLOCKS -> z-role; else -> W/B cvt role.
//
// z-role (R14-proven): 64-row block, 128 thr, 4 warps (2m x 2n), warp 32x32.
// Per 64-K tile: LDG x fp32 (prefetched) -> cvt -> STS + STG xh; cp.async
// A fp16 tile; mma. Epilogue: exact 16th-largest |z| soft mask -> zs fp16.
//
// cvt-role: grid-stride fp32->fp16 over W then B.
// ===========================================================================
__global__ void __launch_bounds__(128)
z_and_cvt_kernel(const float4* __restrict__ x,
                 const float4* __restrict__ W,
                 const float4* __restrict__ B)
{
    if (blockIdx.x >= Z_BLOCKS) {
        // ---- cvt role: W then B ----
        const int nW = N_FIX * D_IN_C / 4;   // 4194304
        const int nB = N_FIX * R_C / 4;      // 65536
        const int total = nW + nB;
        const int cvt_bid = blockIdx.x - Z_BLOCKS;
        int i = cvt_bid * blockDim.x + threadIdx.x;
        const int stride = CVT_BLOCKS * blockDim.x;
        for (; i < total; i += stride) {
            const float4* src; uint2* dst; int j;
            if (i < nW) { src = W; dst = (uint2*)g_wh; j = i; }
            else        { src = B; dst = (uint2*)g_bh; j = i - nW; }
            float4 v = src[j];
            uint2 o;
            o.x = pack2(v.x, v.y);
            o.y = pack2(v.z, v.w);
            dst[j] = o;
        }
        return;
    }

    // ---- z role ----
    extern __shared__ uint32_t smem[];
    uint32_t* As = smem;                  // [2][64][PITCH]  (x tiles)
    uint32_t* Bs = smem + 2 * 64 * PITCH; // [2][64][PITCH]  (A tiles)
    float*    zbuf = (float*)smem;        // [64][65], aliased after MMAs

    const int tid  = threadIdx.x;
    const int lane = tid & 31;
    const int wid  = tid >> 5;
    const int wm   = wid >> 1;
    const int wn   = wid & 1;
    const int bm   = blockIdx.x * 64;

    const int col4 = tid & 15;        // f4 column within k-tile
    const int row0 = tid >> 4;        // base row (thread handles rows row0+8i)

    float acc[2][4][4];
#pragma unroll
    for (int mt = 0; mt < 2; mt++)
#pragma unroll
        for (int nt = 0; nt < 4; nt++)
#pragma unroll
            for (int e = 0; e < 4; e++) acc[mt][nt][e] = 0.0f;

    auto ldg_x = [&](int kb, float4* r) {
#pragma unroll
        for (int i = 0; i < 8; i++)
            r[i] = x[(size_t)(bm + row0 + i * 8) * 1024 + kb * 16 + col4];
    };
    auto cpa_b = [&](int kb, int s) {
        uint32_t* bs = Bs + s * 64 * PITCH;
#pragma unroll
        for (int i = 0; i < 4; i++) {
            int linear = tid + i * 128;
            int row = linear >> 3;
            int cv  = (linear & 7) << 2;
            cp_async16(&bs[row * PITCH + cv],
                       g_ah + (size_t)row * D_IN_P + kb * 32 + cv);
        }
        CPA_COMMIT();
    };
    auto sts_stg = [&](int kb, int s, const float4* r) {
        uint32_t* as = As + s * 64 * PITCH;
        uint2* xo = (uint2*)g_xh;
#pragma unroll
        for (int i = 0; i < 8; i++) {
            uint2 v;
            v.x = pack2(r[i].x, r[i].y);
            v.y = pack2(r[i].z, r[i].w);
            int row = row0 + i * 8;
            *(uint2*)&as[row * PITCH + col4 * 2] = v;
            xo[(size_t)(bm + row) * 1024 + kb * 16 + col4] = v;
        }
    };
    auto mma_tile = [&](int s) {
        const uint32_t* as = As + s * 64 * PITCH + (wm * 32) * PITCH;
        const uint32_t* bs = Bs + s * 64 * PITCH + (wn * 32) * PITCH;
#pragma unroll
        for (int kk = 0; kk < 4; kk++) {
            uint32_t afrag[2][4];
#pragma unroll
            for (int mt = 0; mt < 2; mt++) {
                int r = mt * 16 + (lane >> 2);
                int c = kk * 8 + (lane & 3);
                afrag[mt][0] = as[r * PITCH + c];
                afrag[mt][1] = as[(r + 8) * PITCH + c];
                afrag[mt][2] = as[r * PITCH + c + 4];
                afrag[mt][3] = as[(r + 8) * PITCH + c + 4];
            }
            uint32_t bfrag[4][2];
#pragma unroll
            for (int nt = 0; nt < 4; nt++) {
                int n = nt * 8 + (lane >> 2);
                int c = kk * 8 + (lane & 3);
                bfrag[nt][0] = bs[n * PITCH + c];
                bfrag[nt][1] = bs[n * PITCH + c + 4];
            }
#pragma unroll
            for (int mt = 0; mt < 2; mt++)
#pragma unroll
                for (int nt = 0; nt < 4; nt++)
                    mma_f16(acc[mt][nt], afrag[mt], bfrag[nt]);
        }
    };

    const int KT = D_IN_C / 64;   // 64 (even)
    float4 rA[8], rB[8];
    ldg_x(0, rA);
    cpa_b(0, 0);

    for (int kb2 = 0; kb2 < KT; kb2 += 2) {
        if (kb2 + 1 < KT) { ldg_x(kb2 + 1, rB); cpa_b(kb2 + 1, 1); }
        sts_stg(kb2, 0, rA);
        if (kb2 + 1 < KT) { CPA_WAIT(1); } else { CPA_WAIT(0); }
        __syncthreads();
        mma_tile(0);
        __syncthreads();
        if (kb2 + 1 < KT) {
            if (kb2 + 2 < KT) { ldg_x(kb2 + 2, rA); cpa_b(kb2 + 2, 0); }
            sts_stg(kb2 + 1, 1, rB);
            if (kb2 + 2 < KT) { CPA_WAIT(1); } else { CPA_WAIT(0); }
            __syncthreads();
            mma_tile(1);
            __syncthreads();
        }
    }

    // ---- z -> smem (pitch 65 floats) ----
#pragma unroll
    for (int mt = 0; mt < 2; mt++)
#pragma unroll
        for (int nt = 0; nt < 4; nt++) {
            int r0 = wm * 32 + mt * 16 + (lane >> 2);
            int c0 = wn * 32 + nt * 8 + (lane & 3) * 2;
            zbuf[r0 * 65 + c0]           = acc[mt][nt][0];
            zbuf[r0 * 65 + c0 + 1]       = acc[mt][nt][1];
            zbuf[(r0 + 8) * 65 + c0]     = acc[mt][nt][2];
            zbuf[(r0 + 8) * 65 + c0 + 1] = acc[mt][nt][3];
        }
    __syncthreads();

    // ---- soft top-k per row; warp w handles rows w*16 .. w*16+15 ----
    const float inv_t = 1.0f / TEMP_C;
    for (int rr = 0; rr < 16; rr++) {
        const int row = wid * 16 + rr;
        float z0 = zbuf[row * 65 + lane];
        float z1 = zbuf[row * 65 + lane + 32];
        float v0 = fabsf(z0), v1 = fabsf(z1);
        bool a0 = true, a1 = true;
        float thr = 0.0f;
#pragma unroll 1
        for (int it = 0; it < KSEL_C; it++) {
            float m = fmaxf(a0 ? v0 : -1.0f, a1 ? v1 : -1.0f);
#pragma unroll
            for (int off = 16; off; off >>= 1)
                m = fmaxf(m, __shfl_xor_sync(0xffffffffu, m, off));
            thr = m;
            unsigned b = __ballot_sync(0xffffffffu, a0 && v0 == m);
            if (b) {
                if (lane == (__ffs(b) - 1)) a0 = false;
            } else {
                unsigned b2 = __ballot_sync(0xffffffffu, a1 && v1 == m);
                if (lane == (__ffs(b2) - 1)) a1 = false;
            }
        }
        float zs0 = z0 * (1.0f / (1.0f + expf(-(v0 - thr) * inv_t)));
        float zs1 = z1 * (1.0f / (1.0f + expf(-(v1 - thr) * inv_t)));
        zbuf[row * 65 + lane]      = zs0;
        zbuf[row * 65 + lane + 32] = zs1;
        __syncwarp();
        g_zsh[(size_t)(bm + row) * R_P + lane] =
            pack2(zbuf[row * 65 + 2 * lane], zbuf[row * 65 + 2 * lane + 1]);
        __syncwarp();
    }
}

// ===========================================================================
// Kernel 3: MAIN GEMM (R14 record structure, byte-identical schedule).
// 128x128 CTA, 128 threads, 4 warps (2m x 2n), warp tile 64x64.
// K: 64 main tiles + 1 LoRA tile (zs @ B^T). 2-stage cp.async, pitch-36.
// ===========================================================================
__global__ void __launch_bounds__(128)
gemm_main(const float* __restrict__ bias, float* __restrict__ out)
{
    constexpr int BM = 128, BN = 128, MT = 4, NT = 8;
    extern __shared__ uint32_t smem[];
    uint32_t* As = smem;                    // [2][BM][PITCH]
    uint32_t* Bs = smem + 2 * BM * PITCH;   // [2][BN][PITCH]

    const int tid  = threadIdx.x;
    const int lane = tid & 31;
    const int wid  = tid >> 5;
    const int wm   = wid >> 1;
    const int wn   = wid & 1;

    const int bm = blockIdx.y * BM;
    const int bn = blockIdx.x * BN;

    float acc[MT][NT][4];
#pragma unroll
    for (int mt = 0; mt < MT; mt++)
#pragma unroll
        for (int nt = 0; nt < NT; nt++)
#pragma unroll
            for (int i = 0; i < 4; i++) acc[mt][nt][i] = 0.0f;

    const int KT_main = D_IN_C / 64;        // 64
    const int KT = KT_main + 1;             // + LoRA tile

    auto issue_copy = [&](int kb, int stage) {
        uint32_t* as = As + stage * BM * PITCH;
        uint32_t* bs = Bs + stage * BN * PITCH;
        const bool main_k = (kb < KT_main);
#pragma unroll
        for (int i = 0; i < BM / 16; i++) {
            int linear = tid + i * 128;
            int row = linear >> 3;
            int cv  = (linear & 7) << 2;
            const uint32_t* src = main_k
                ? g_xh  + (size_t)(bm + row) * D_IN_P + (size_t)kb * 32 + cv
                : g_zsh + (size_t)(bm + row) * R_P + cv;
            cp_async16(&as[row * PITCH + cv], src);
        }
#pragma unroll
        for (int i = 0; i < BN / 16; i++) {
            int linear = tid + i * 128;
            int row = linear >> 3;
            int cv  = (linear & 7) << 2;
            const uint32_t* src = main_k
                ? g_wh + (size_t)(bn + row) * D_IN_P + (size_t)kb * 32 + cv
                : g_bh + (size_t)(bn + row) * R_P + cv;
            cp_async16(&bs[row * PITCH + cv], src);
        }
        CPA_COMMIT();
    };

    issue_copy(0, 0);

    for (int kb = 0; kb < KT; kb++) {
        const int stage = kb & 1;
        if (kb + 1 < KT) {
            issue_copy(kb + 1, (kb + 1) & 1);
            CPA_WAIT(1);
        } else {
            CPA_WAIT(0);
        }
        __syncthreads();

        const uint32_t* as = As + stage * BM * PITCH + (wm * 64) * PITCH;
        const uint32_t* bs = Bs + stage * BN * PITCH + (wn * 64) * PITCH;

#pragma unroll
        for (int kk = 0; kk < 4; kk++) {
            uint32_t afrag[MT][4];
#pragma unroll
            for (int mt = 0; mt < MT; mt++) {
                int r = mt * 16 + (lane >> 2);
                int c = kk * 8 + (lane & 3);
                afrag[mt][0] = as[r * PITCH + c];
                afrag[mt][1] = as[(r + 8) * PITCH + c];
                afrag[mt][2] = as[r * PITCH + c + 4];
                afrag[mt][3] = as[(r + 8) * PITCH + c + 4];
            }
            uint32_t bfrag[NT][2];
#pragma unroll
            for (int nt = 0; nt < NT; nt++) {
                int n = nt * 8 + (lane >> 2);
                int c = kk * 8 + (lane & 3);
                bfrag[nt][0] = bs[n * PITCH + c];
                bfrag[nt][1] = bs[n * PITCH + c + 4];
            }
#pragma unroll
            for (int mt = 0; mt < MT; mt++)
#pragma unroll
                for (int nt = 0; nt < NT; nt++)
                    mma_f16(acc[mt][nt], afrag[mt], bfrag[nt]);
        }
        __syncthreads();
    }

    // Epilogue: + bias, fp32 store
#pragma unroll
    for (int mt = 0; mt < MT; mt++) {
#pragma unroll
        for (int nt = 0; nt < NT; nt++) {
            int r0 = bm + wm * 64 + mt * 16 + (lane >> 2);
            int c0 = bn + wn * 64 + nt * 8 + (lane & 3) * 2;
            float b0 = __ldg(&bias[c0]), b1 = __ldg(&bias[c0 + 1]);
            float2 v0 = make_float2(acc[mt][nt][0] + b0, acc[mt][nt][1] + b1);
            float2 v1 = make_float2(acc[mt][nt][2] + b0, acc[mt][nt][3] + b1);
            *(float2*)&out[(size_t)r0 * N_FIX + c0]       = v0;
            *(float2*)&out[(size_t)(r0 + 8) * N_FIX + c0] = v1;
        }
    }
}

// ---------------------------------------------------------------------------
extern "C" void kernel_launch(void* const* d_in, const int* in_sizes, int n_in,
                              void* d_out, int out_size)
{
    const float* x    = (const float*)d_in[0];
    const float* Amat = (const float*)d_in[1];
    const float* Bmat = (const float*)d_in[2];
    const float* Wmat = (const float*)d_in[3];
    const float* bias = (const float*)d_in[4];
    float* out = (float*)d_out;

    const int M = in_sizes[0] / D_IN_C;          // 8192
    const int N = in_sizes[4];                   // 4096

    constexpr int SMEM_MAIN = 2 * (128 + 128) * PITCH * 4;  // 73728 B
    constexpr int SMEM_Z    = 2 * (64 + 64) * PITCH * 4;    // 36864 B
    cudaFuncSetAttribute(gemm_main,
                         cudaFuncAttributeMaxDynamicSharedMemorySize, SMEM_MAIN);
    cudaFuncSetAttribute(z_and_cvt_kernel,
                         cudaFuncAttributeMaxDynamicSharedMemorySize, SMEM_Z);

    // 1) A -> fp16 (tiny)
    cvt_a_kernel<<<64, 128>>>((const float4*)Amat);

    // 2) merged: z-role (x cvt + z + topk) || cvt-role (W/B -> fp16)
    z_and_cvt_kernel<<<Z_BLOCKS + CVT_BLOCKS, 128, SMEM_Z>>>(
        (const float4*)x, (const float4*)Wmat, (const float4*)Bmat);

    // 3) out = x@W^T + bias + zs@B^T (LoRA = extra K-tile)
    {
        dim3 grid(N / 128, M / 128);
        gemm_main<<<grid, 128, SMEM_MAIN>>>(bias, out);
    }
}